// round 5
// baseline (speedup 1.0000x reference)
#include <cuda_runtime.h>

#define T_STEPS 256
#define NPRE    1024
#define NPOST   1024
#define K       16            // decay window: 2^-16 = 1.5e-5 rel truncation, 60x under 1e-3
#define ROWS    8             // output rows per block
#define NBLK    (NPRE / ROWS) // 128 blocks -> fills the 148-SM chip in one wave
#define NTHR    512

// e[i][j] = x[i]*q_last[j] - p_last[i]*y[j]
// x = sum_t pre[t][i] * 2^(t-T)  (TE=1 wipes e history; TP=TN=2 give geometric traces)
__global__ __launch_bounds__(NTHR, 2)
void stdp_fused_kernel(const float* __restrict__ pre,
                       const float* __restrict__ post,
                       float* __restrict__ e) {
    __shared__ float sy[NPOST];   // y trace
    __shared__ float sq[NPOST];   // post[T-1][:]
    __shared__ float sx[ROWS];    // x trace for this block's rows
    __shared__ float sp[ROWS];    // pre[T-1][block rows]

    const int tid = threadIdx.x;

    // ---- Phase A: y[j], q_last[j]; 512 threads x 2 columns, coalesced ----
    {
        const float* __restrict__ b = post + (size_t)(T_STEPS - K) * NPOST;
        float acc0 = 0.0f, acc1 = 0.0f;
        #pragma unroll
        for (int k = 0; k < K; k++) {
            const float w = exp2f((float)(k - K));   // constant-folded after unroll
            acc0 = fmaf(b[(size_t)k * NPOST + tid],       w, acc0);
            acc1 = fmaf(b[(size_t)k * NPOST + tid + 512], w, acc1);
        }
        sy[tid]       = acc0;
        sy[tid + 512] = acc1;
        sq[tid]       = b[(size_t)(K - 1) * NPOST + tid];
        sq[tid + 512] = b[(size_t)(K - 1) * NPOST + tid + 512];
    }

    // ---- Phase B: x[i], p_last[i]; one warp per row, lanes 0..K-1 active ----
    {
        const int wid  = tid >> 5;
        const int lane = tid & 31;
        if (wid < ROWS) {
            const int i = blockIdx.x * ROWS + wid;
            float v = 0.0f;
            if (lane < K) {
                v = pre[(size_t)(T_STEPS - K + lane) * NPRE + i]
                    * exp2f((float)(lane - K));
            }
            #pragma unroll
            for (int o = 16; o; o >>= 1) v += __shfl_xor_sync(0xFFFFFFFFu, v, o);
            if (lane == 0) sx[wid] = v;
            if (lane == K - 1) sp[wid] = pre[(size_t)(T_STEPS - 1) * NPRE + i];
        }
    }

    __syncthreads();

    // ---- Phase C: rank-2 outer product, 4x STG.128 per thread ----
    const int col4 = tid & 255;   // columns [col4*4 .. col4*4+3]
    const int rsub = tid >> 8;    // 0..1 -> row half
    const float4 y4 = reinterpret_cast<const float4*>(sy)[col4];
    const float4 q4 = reinterpret_cast<const float4*>(sq)[col4];
    float4* __restrict__ out4 = reinterpret_cast<float4*>(e);

    #pragma unroll
    for (int rr = 0; rr < ROWS / 2; rr++) {
        const int r = rsub * (ROWS / 2) + rr;
        const int i = blockIdx.x * ROWS + r;
        const float xi = sx[r];
        const float pi = sp[r];
        float4 o;
        o.x = fmaf(xi, q4.x, -pi * y4.x);
        o.y = fmaf(xi, q4.y, -pi * y4.y);
        o.z = fmaf(xi, q4.z, -pi * y4.z);
        o.w = fmaf(xi, q4.w, -pi * y4.w);
        out4[(size_t)i * (NPOST / 4) + col4] = o;
    }
}

extern "C" void kernel_launch(void* const* d_in, const int* in_sizes, int n_in,
                              void* d_out, int out_size) {
    const float* pre  = (const float*)d_in[0];   // [T, NPRE]
    const float* post = (const float*)d_in[1];   // [T, NPOST]
    float* e = (float*)d_out;                    // [NPRE, NPOST]

    stdp_fused_kernel<<<NBLK, NTHR>>>(pre, post, e);
}

// round 8
// speedup vs baseline: 1.6000x; 1.6000x over previous
#include <cuda_runtime.h>

#define T_STEPS 256
#define NPRE    1024
#define NPOST   1024
#define K       16            // 2^-16 = 1.5e-5 rel truncation; 60x under 1e-3 (measured 3.2e-5)
#define ROWS    8             // 128 blocks x 1024 thr: 32 warps/SM AND ~full chip coverage
#define NBLK    (NPRE / ROWS) // 128
#define NTHR    1024

// e[i][j] = x[i]*q_last[j] - p_last[i]*y[j]
// x = sum_t pre[t][i] * 2^(t-T)  (TE=1 wipes e history; TP=TN=2 give geometric traces)
__global__ __launch_bounds__(NTHR, 1)
void stdp_fused_kernel(const float* __restrict__ pre,
                       const float* __restrict__ post,
                       float* __restrict__ e) {
    __shared__ float sy[NPOST];   // y trace
    __shared__ float sq[NPOST];   // post[T-1][:]
    __shared__ float sx[ROWS];    // x trace for this block's rows
    __shared__ float sp[ROWS];    // pre[T-1][block rows]

    const int tid = threadIdx.x;

    // ---- Phase A: y[tid], q_last[tid]; one column per thread, fully coalesced.
    //      17 -> 16 loads: the k=K-1 load doubles as q_last.
    {
        const float* __restrict__ b = post + (size_t)(T_STEPS - K) * NPOST + tid;
        float acc = 0.0f;
        float last = 0.0f;
        #pragma unroll
        for (int k = 0; k < K; k++) {
            const float v = b[(size_t)k * NPOST];
            last = v;                                  // k = K-1 survives
            acc = fmaf(v, exp2f((float)(k - K)), acc); // weight const-folded
        }
        sy[tid] = acc;
        sq[tid] = last;
    }

    // ---- Phase B: x[i], p_last[i]; one warp per row (warps 0..7), lanes 0..15 ----
    {
        const int wid  = tid >> 5;
        const int lane = tid & 31;
        if (wid < ROWS) {
            const int i = blockIdx.x * ROWS + wid;
            float v = 0.0f;
            if (lane < K) {
                v = pre[(size_t)(T_STEPS - K + lane) * NPRE + i]
                    * exp2f((float)(lane - K));
            }
            #pragma unroll
            for (int o = 8; o; o >>= 1) v += __shfl_xor_sync(0xFFFFFFFFu, v, o);
            if (lane == 0)     sx[wid] = v;            // lanes 0..15 hold the sum
            if (lane == K - 1) sp[wid] = pre[(size_t)(T_STEPS - 1) * NPRE + i];
        }
    }

    __syncthreads();

    // ---- Phase C: rank-2 outer product, 2x STG.128 per thread ----
    const int col4 = tid & 255;   // columns [4*col4 .. 4*col4+3]
    const int rsub = tid >> 8;    // 0..3
    const float4 y4 = reinterpret_cast<const float4*>(sy)[col4];
    const float4 q4 = reinterpret_cast<const float4*>(sq)[col4];
    float4* __restrict__ out4 = reinterpret_cast<float4*>(e);

    #pragma unroll
    for (int rr = 0; rr < ROWS / 4; rr++) {            // 2 iterations
        const int r = rsub * (ROWS / 4) + rr;
        const int i = blockIdx.x * ROWS + r;
        const float xi = sx[r];
        const float pi = sp[r];
        float4 o;
        o.x = fmaf(xi, q4.x, -pi * y4.x);
        o.y = fmaf(xi, q4.y, -pi * y4.y);
        o.z = fmaf(xi, q4.z, -pi * y4.z);
        o.w = fmaf(xi, q4.w, -pi * y4.w);
        out4[(size_t)i * (NPOST / 4) + col4] = o;
    }
}

extern "C" void kernel_launch(void* const* d_in, const int* in_sizes, int n_in,
                              void* d_out, int out_size) {
    const float* pre  = (const float*)d_in[0];   // [T, NPRE]
    const float* post = (const float*)d_in[1];   // [T, NPOST]
    float* e = (float*)d_out;                    // [NPRE, NPOST]

    stdp_fused_kernel<<<NBLK, NTHR>>>(pre, post, e);
}

// round 10
// speedup vs baseline: 1.6618x; 1.0386x over previous
#include <cuda_runtime.h>

#define T_STEPS 256
#define NPRE    1024
#define NPOST   1024
#define K       16            // 2^-16 rel truncation; measured rel_err 3.2e-5, 30x under 1e-3
#define ROWS    8             // 128 blocks x 1024 thr: 32 warps/SM, ~full chip in one wave
#define NBLK    (NPRE / ROWS) // 128
#define NTHR    1024

// e[i][j] = x[i]*q_last[j] - p_last[i]*y[j]
// x = sum_t pre[t][i] * 2^(t-T)  (TE=1 wipes e history; TP=TN=2 give geometric traces)
__global__ __launch_bounds__(NTHR, 1)
void stdp_fused_kernel(const float* __restrict__ pre,
                       const float* __restrict__ post,
                       float* __restrict__ e) {
    __shared__ float4 s_part[4][NPOST / 4];  // per-k-quarter partial y (float4 cols)
    __shared__ float4 s_q4[NPOST / 4];       // post[T-1][:]
    __shared__ float  sx[ROWS];              // x trace for this block's rows
    __shared__ float  sp[ROWS];              // pre[T-1][block rows]

    const int tid  = threadIdx.x;
    const int col4 = tid & 255;              // float4 column group 0..255
    const int kq   = tid >> 8;               // k-quarter 0..3

    // ---- Phase A: partial y for 4 timesteps, 4 columns (LDG.128) ----
    {
        const float4* __restrict__ b =
            reinterpret_cast<const float4*>(post + (size_t)(T_STEPS - K + kq * 4) * NPOST) + col4;
        const float4 v0 = b[0 * (NPOST / 4)];
        const float4 v1 = b[1 * (NPOST / 4)];
        const float4 v2 = b[2 * (NPOST / 4)];
        const float4 v3 = b[3 * (NPOST / 4)];

        // weight(k) = 2^(k-16) = 2^(4*kq-16) * {1,2,4,8}; exact ldexp via exponent bits
        const float wb = __uint_as_float((unsigned)(127 - K + 4 * kq) << 23);

        float4 s;
        s.x = wb * fmaf(8.0f, v3.x, fmaf(4.0f, v2.x, fmaf(2.0f, v1.x, v0.x)));
        s.y = wb * fmaf(8.0f, v3.y, fmaf(4.0f, v2.y, fmaf(2.0f, v1.y, v0.y)));
        s.z = wb * fmaf(8.0f, v3.z, fmaf(4.0f, v2.z, fmaf(2.0f, v1.z, v0.z)));
        s.w = wb * fmaf(8.0f, v3.w, fmaf(4.0f, v2.w, fmaf(2.0f, v1.w, v0.w)));
        s_part[kq][col4] = s;

        if (kq == 3) s_q4[col4] = v3;        // k = 15 load doubles as q_last
    }

    // ---- Phase B: x[i], p_last[i]; warps 8..15, one warp per row ----
    {
        const int wid  = tid >> 5;
        const int lane = tid & 31;
        if (wid >= 8 && wid < 8 + ROWS) {
            const int r = wid - 8;
            const int i = blockIdx.x * ROWS + r;
            float v = 0.0f;
            if (lane < K) {
                v = pre[(size_t)(T_STEPS - K + lane) * NPRE + i]
                    * __uint_as_float((unsigned)(127 - K + lane) << 23);  // exact 2^(lane-16)
            }
            #pragma unroll
            for (int o = 8; o; o >>= 1) v += __shfl_xor_sync(0xFFFFFFFFu, v, o);
            if (lane == 0)     sx[r] = v;    // lanes 0..15 hold the sum
            if (lane == K - 1) sp[r] = pre[(size_t)(T_STEPS - 1) * NPRE + i];
        }
    }

    __syncthreads();

    // ---- Phase C: sum partials inline, rank-2 outer product, 2x STG.128 ----
    const float4 p0 = s_part[0][col4];
    const float4 p1 = s_part[1][col4];
    const float4 p2 = s_part[2][col4];
    const float4 p3 = s_part[3][col4];
    const float4 q4 = s_q4[col4];

    float4 y4;
    y4.x = (p0.x + p1.x) + (p2.x + p3.x);
    y4.y = (p0.y + p1.y) + (p2.y + p3.y);
    y4.z = (p0.z + p1.z) + (p2.z + p3.z);
    y4.w = (p0.w + p1.w) + (p2.w + p3.w);

    float4* __restrict__ out4 = reinterpret_cast<float4*>(e);

    #pragma unroll
    for (int rr = 0; rr < 2; rr++) {
        const int r = kq * 2 + rr;           // 4 quarters x 2 rows = 8 rows
        const int i = blockIdx.x * ROWS + r;
        const float xi = sx[r];
        const float pi = sp[r];
        float4 o;
        o.x = fmaf(xi, q4.x, -pi * y4.x);
        o.y = fmaf(xi, q4.y, -pi * y4.y);
        o.z = fmaf(xi, q4.z, -pi * y4.z);
        o.w = fmaf(xi, q4.w, -pi * y4.w);
        out4[(size_t)i * (NPOST / 4) + col4] = o;
    }
}

extern "C" void kernel_launch(void* const* d_in, const int* in_sizes, int n_in,
                              void* d_out, int out_size) {
    const float* pre  = (const float*)d_in[0];   // [T, NPRE]
    const float* post = (const float*)d_in[1];   // [T, NPOST]
    float* e = (float*)d_out;                    // [NPRE, NPOST]

    stdp_fused_kernel<<<NBLK, NTHR>>>(pre, post, e);
}